// round 17
// baseline (speedup 1.0000x reference)
#include <cuda_runtime.h>
#include <cstdint>
#include <math.h>

typedef unsigned long long ull;

static constexpr int B_ROWS = 262144;
static constexpr int L_STEPS = 20;
static constexpr int TPB = 64;                       // 2 warps, 1 row/thread
static constexpr int ROWS_PER_CTA = TPB;             // 64
static constexpr int GRID = B_ROWS / ROWS_PER_CTA;   // 4096

// ---- constant memory: broadcast operands (const port) ----
__constant__ float cWdr[2500];   // Wdrift [50,50] row-major (even rows read here)
__constant__ float cBdr[50];
__constant__ float cBd[50];
__constant__ float cB1[100];
__constant__ float cW2[100];
__constant__ float cWfc[100];
__constant__ float cB2[1];
__constant__ float cBfc[2];

// ---- shared memory (floats): one 5200-float region, phase-overlaid ----
// Phase 1a: sWd[4800]  (Wd rows padded to 96)
// Phase 1b: sW1[5200]  (W1 stride 52)
// Phase 2 : sWdrOdd[1300] @ 0  +  noise[3200] @ 1300 (warp w: [1300+1600w, +1600))
static constexpr int OFF_NOISE  = 1300;              // 5200B, 16B aligned
static constexpr int SMEM_FLOATS = 5200;
static constexpr int SMEM_BYTES  = SMEM_FLOATS * 4;  // 20800 -> 8 CTAs/SM (reg cap 128)

// ---- packed f32x2 helpers (Blackwell 2x-fp32 path; PTX-only) ----
static __device__ __forceinline__ ull ffma2(ull a, ull b, ull c) {
    ull d;
    asm("fma.rn.f32x2 %0, %1, %2, %3;" : "=l"(d) : "l"(a), "l"(b), "l"(c));
    return d;
}
static __device__ __forceinline__ ull pack2(float lo, float hi) {
    ull r;
    asm("mov.b64 %0, {%1, %2};" : "=l"(r) : "f"(lo), "f"(hi));
    return r;
}
static __device__ __forceinline__ void unpack2(ull v, float& lo, float& hi) {
    asm("mov.b64 {%0, %1}, %2;" : "=f"(lo), "=f"(hi) : "l"(v));
}

static __device__ __forceinline__ unsigned smem_u32(const void* p) {
    return (unsigned)__cvta_generic_to_shared(p);
}
static __device__ __forceinline__ void cp16(void* sdst, const void* gsrc) {
    asm volatile("cp.async.cg.shared.global [%0], [%1], 16;"
                 :: "r"(smem_u32(sdst)), "l"(gsrc) : "memory");
}

// Prologue dot for one row, chunked partial sums (bounded register pressure).
static __device__ __forceinline__ void prologue_row(const float* __restrict__ xrow,
                                                    const float* __restrict__ sWd,
                                                    ull* __restrict__ out2) {
#pragma unroll
    for (int p = 0; p < 25; ++p) out2[p] = pack2(cBd[2 * p], cBd[2 * p + 1]);

    for (int c = 0; c < 3; ++c) {
        ull xv[16];
        const ull* xr = (const ull*)xrow + c * 16;
        if (c < 2) {
#pragma unroll
            for (int t = 0; t < 16; ++t) xv[t] = xr[t];
        } else {
#pragma unroll
            for (int t = 0; t < 13; ++t) xv[t] = xr[t];
            xv[13] = 0ull; xv[14] = 0ull; xv[15] = 0ull;   // Wd cols 90..95 are 0
        }
#pragma unroll 5
        for (int p = 0; p < 25; ++p) {
            const ulonglong2* w0 = (const ulonglong2*)(sWd + (2 * p) * 96 + c * 32);
            const ulonglong2* w1 = (const ulonglong2*)(sWd + (2 * p + 1) * 96 + c * 32);
            ull a0 = 0ull, a1 = 0ull;
#pragma unroll
            for (int q = 0; q < 8; ++q) {
                ulonglong2 wa = w0[q];
                a0 = ffma2(wa.x, xv[2 * q],     a0);
                a0 = ffma2(wa.y, xv[2 * q + 1], a0);
                ulonglong2 wb = w1[q];
                a1 = ffma2(wb.x, xv[2 * q],     a1);
                a1 = ffma2(wb.y, xv[2 * q + 1], a1);
            }
            float l0, h0, l1, h1, o0, o1;
            unpack2(a0, l0, h0);
            unpack2(a1, l1, h1);
            unpack2(out2[p], o0, o1);
            out2[p] = pack2(o0 + l0 + h0, o1 + l1 + h1);
        }
    }
}

__global__ void __launch_bounds__(TPB, 8)   // 8 CTAs/SM -> 16 warps/SM, reg cap 128
sdenet_kernel(const float* __restrict__ x,      // [B,90]
              const float* __restrict__ Wd,     // [50,90]
              const float* __restrict__ bd,     // [50]
              const float* __restrict__ Wdrift, // [50,50]
              const float* __restrict__ bdrift, // [50]
              const float* __restrict__ W1,     // [100,50]
              const float* __restrict__ b1,     // [100]
              const float* __restrict__ W2,     // [1,100]
              const float* __restrict__ b2,     // [1]
              const float* __restrict__ Wfc,    // [2,50]
              const float* __restrict__ bfc,    // [2]
              const float* __restrict__ noise,  // [L,B,50]
              float* __restrict__ out)          // [2*B] = mean(B) ++ sigma(B)
{
    extern __shared__ float smem[];
    float* sWd     = smem;                 // phase-1a alias (4800 <= 5200)
    float* sW1     = smem;                 // phase-1b alias (5200)
    float* sWdrOdd = smem;                 // phase-2: [0,1300)
    float* sNoise  = smem + OFF_NOISE;     // phase-2: [1300,4500)

    const int tid  = threadIdx.x;
    const int warp = tid >> 5;             // 0 or 1
    const int lane = tid & 31;
    const size_t rowBase = (size_t)blockIdx.x * ROWS_PER_CTA;
    const int row = (int)rowBase + 32 * warp + lane;   // 1 row/thread

    // Warp-private noise slice: 32 rows = 1600 floats, contiguous (gmem & smem)
    float* wSlice = sNoise + warp * 1600;
    const size_t wSliceOff = rowBase * 50 + (size_t)warp * 1600;

    // ---- phase 1a: stage Wd (padded 96) ----
    for (int i = tid; i < 4800; i += TPB) {
        int r = i / 96, k = i - r * 96;
        sWd[i] = (k < 90) ? Wd[r * 90 + k] : 0.0f;
    }
    __syncthreads();

    // ================= prologue: out = x @ Wd^T + bd =================
    ull out2[25];
    prologue_row(x + (size_t)row * 90, sWd, out2);
    __syncthreads();   // done reading Wd

    // ---- phase 1b: stage W1 ----
    for (int i = tid; i < 5000; i += TPB) {
        int m = i / 50, k = i - m * 50;
        sW1[m * 52 + k] = W1[i];
    }
    __syncthreads();

    // ====== diffusion = 0.5*sigmoid(relu(out@W1^T+b1) @ W2^T + b2) ======
    float dacc = cB2[0];
#pragma unroll 2
    for (int m = 0; m < 100; ++m) {
        const float* wrow = sW1 + m * 52;
        const ulonglong2* w2r = (const ulonglong2*)wrow;
        ull aA = 0ull, aB = 0ull;          // 2 chains for ILP
#pragma unroll
        for (int q = 0; q < 12; ++q) {
            ulonglong2 w = w2r[q];
            aA = ffma2(w.x, out2[2 * q],     aA);
            aB = ffma2(w.y, out2[2 * q + 1], aB);
        }
        aA = ffma2(*(const ull*)(wrow + 48), out2[24], aA);
        float lA, hA, lB, hB;
        unpack2(aA, lA, hA);
        unpack2(aB, lB, hB);
        dacc = fmaf(cW2[m], fmaxf(lA + hA + lB + hB + cB1[m], 0.0f), dacc);
    }
    const float dt   = 4.0f / 20.0f;
    const float sqdt = sqrtf(dt);
    const float ds   = (0.5f / (1.0f + expf(-dacc))) * sqdt;
    const ull ds2 = pack2(ds, ds);
    const ull dt2 = pack2(dt, dt);
    __syncthreads();   // done reading W1; region free for phase-2 residents

    // ---- phase 2 staging: odd Wdrift rows; prefetch step-0 noise ----
    for (int i = tid; i < 1300; i += TPB) {
        int o = i / 52, k = i - o * 52;
        sWdrOdd[i] = (k < 50) ? Wdrift[(2 * o + 1) * 50 + k] : 0.0f;
    }
    {
        const float* nsrc = noise + wSliceOff;
#pragma unroll
        for (int i = 0; i < 13; ++i) {
            int c = lane + 32 * i;
            if (c < 400) cp16(wSlice + c * 4, nsrc + c * 4);
        }
        asm volatile("cp.async.commit_group;" ::: "memory");
    }
    __syncthreads();   // sWdrOdd visible CTA-wide (LAST CTA barrier)

    // Constant-space views of even Wdrift rows.
    const ulonglong2* cW16 = (const ulonglong2*)cWdr;
    const ull*        cW8  = (const ull*)cWdr;
    const ull*        cBdr2 = (const ull*)cBdr;

    // ================= main SDE loop: warp-scoped sync only =================
#pragma unroll 1
    for (int l = 0; l < L_STEPS; ++l) {
        asm volatile("cp.async.wait_group 0;" ::: "memory");   // own group done
        __syncwarp();   // slice visible warp-wide

        const ull* nrow = (const ull*)(wSlice + lane * 50);

        ull dnew[25];
#pragma unroll 5
        for (int p = 0; p < 25; ++p) {
            const ulonglong2* w02 = cW16 + 25 * p;            // even row: const port
            const float* w1 = sWdrOdd + p * 52;               // odd row: L1 port
            const ulonglong2* w12 = (const ulonglong2*)w1;
            // 4 accumulator chains (2 per output) for fma-pipe slack
            ull a0x = 0ull, a0y = 0ull, a1x = 0ull, a1y = 0ull;
#pragma unroll
            for (int q = 0; q < 12; ++q) {
                ulonglong2 wa = w02[q];
                a0x = ffma2(wa.x, out2[2 * q],     a0x);
                a0y = ffma2(wa.y, out2[2 * q + 1], a0y);
                ulonglong2 wb = w12[q];
                a1x = ffma2(wb.x, out2[2 * q],     a1x);
                a1y = ffma2(wb.y, out2[2 * q + 1], a1y);
            }
            a0x = ffma2(cW8[50 * p + 24],      out2[24], a0x);
            a1x = ffma2(*(const ull*)(w1 + 48), out2[24], a1x);

            float bd0, bd1;
            unpack2(cBdr2[p], bd0, bd1);
            float l0x, h0x, l0y, h0y, l1x, h1x, l1y, h1y;
            unpack2(a0x, l0x, h0x);
            unpack2(a0y, l0y, h0y);
            unpack2(a1x, l1x, h1x);
            unpack2(a1y, l1y, h1y);
            float s0 = fmaxf(l0x + h0x + l0y + h0y + bd0, 0.0f);
            float s1 = fmaxf(l1x + h1x + l1y + h1y + bd1, 0.0f);
            ull nv = ffma2(dt2, pack2(s0, s1), out2[p]);
            dnew[p] = ffma2(ds2, nrow[p], nv);
        }
#pragma unroll
        for (int p = 0; p < 25; ++p) out2[p] = dnew[p];

        __syncwarp();   // all lanes done READING the slice before overwrite

        if (l + 1 < L_STEPS) {
            const float* nsrc = noise + (size_t)(l + 1) * B_ROWS * 50 + wSliceOff;
#pragma unroll
            for (int i = 0; i < 13; ++i) {
                int c = lane + 32 * i;
                if (c < 400) cp16(wSlice + c * 4, nsrc + c * 4);
            }
            asm volatile("cp.async.commit_group;" ::: "memory");
        }
    }

    // ================= epilogue: relu(out) @ Wfc^T + bfc -> (mean, sigma) =================
    const ull* w0 = (const ull*)(cWfc);
    const ull* w1 = (const ull*)(cWfc + 50);
    ull a0 = 0ull, a1 = 0ull;
#pragma unroll
    for (int p = 0; p < 25; ++p) {
        float lo, hi;
        unpack2(out2[p], lo, hi);
        ull r = pack2(fmaxf(lo, 0.0f), fmaxf(hi, 0.0f));
        a0 = ffma2(w0[p], r, a0);
        a1 = ffma2(w1[p], r, a1);
    }
    float m0, m1, z0, z1;
    unpack2(a0, m0, m1);
    unpack2(a1, z0, z1);
    const float mean = m0 + m1 + cBfc[0];
    const float z    = z0 + z1 + cBfc[1];
    const float sp   = log1pf(expf(-fabsf(z))) + fmaxf(z, 0.0f);
    out[row] = mean;
    out[B_ROWS + row] = sp + 0.001f;
}

extern "C" void kernel_launch(void* const* d_in, const int* in_sizes, int n_in,
                              void* d_out, int out_size) {
    (void)in_sizes; (void)n_in; (void)out_size;
    const float* x      = (const float*)d_in[0];
    const float* Wd     = (const float*)d_in[1];
    const float* bd     = (const float*)d_in[2];
    const float* Wdrift = (const float*)d_in[3];
    const float* bdrift = (const float*)d_in[4];
    const float* W1     = (const float*)d_in[5];
    const float* b1     = (const float*)d_in[6];
    const float* W2     = (const float*)d_in[7];
    const float* b2     = (const float*)d_in[8];
    const float* Wfc    = (const float*)d_in[9];
    const float* bfc    = (const float*)d_in[10];
    const float* noise  = (const float*)d_in[11];
    float* out = (float*)d_out;

    cudaMemcpyToSymbolAsync(cWdr, Wdrift, 2500 * sizeof(float), 0, cudaMemcpyDeviceToDevice);
    cudaMemcpyToSymbolAsync(cBdr, bdrift,   50 * sizeof(float), 0, cudaMemcpyDeviceToDevice);
    cudaMemcpyToSymbolAsync(cBd,  bd,       50 * sizeof(float), 0, cudaMemcpyDeviceToDevice);
    cudaMemcpyToSymbolAsync(cB1,  b1,      100 * sizeof(float), 0, cudaMemcpyDeviceToDevice);
    cudaMemcpyToSymbolAsync(cW2,  W2,      100 * sizeof(float), 0, cudaMemcpyDeviceToDevice);
    cudaMemcpyToSymbolAsync(cWfc, Wfc,     100 * sizeof(float), 0, cudaMemcpyDeviceToDevice);
    cudaMemcpyToSymbolAsync(cB2,  b2,        1 * sizeof(float), 0, cudaMemcpyDeviceToDevice);
    cudaMemcpyToSymbolAsync(cBfc, bfc,       2 * sizeof(float), 0, cudaMemcpyDeviceToDevice);

    cudaFuncSetAttribute(sdenet_kernel,
                         cudaFuncAttributeMaxDynamicSharedMemorySize, SMEM_BYTES);
    sdenet_kernel<<<GRID, TPB, SMEM_BYTES>>>(x, Wd, bd, Wdrift, bdrift,
                                             W1, b1, W2, b2, Wfc, bfc, noise, out);
}